// round 2
// baseline (speedup 1.0000x reference)
#include <cuda_runtime.h>
#include <cstdint>
#include <math.h>

#define Bn 4
#define Nn 256
#define Tn 128
#define Fn 64
#define Kn 8
#define Hn 256

// scratch (static device globals; no runtime allocation)
__device__ float g_ht[Bn*Tn*Nn*Hn];    // h transposed: [b][t][n][h]
__device__ float g_agg[Bn*Tn*Nn*Hn];   // lag-graph aggregate: [b][t][i][h]
__device__ float g_AnT[Kn*Nn*Nn];      // normalized A, transposed: [k][j][i]
__device__ float g_part[256*256];      // ctx partial sums
__device__ float g_ctx[Bn*Fn];         // ctx mean per (b,f)
__device__ float g_alpha[Bn*Kn];       // gate values

__device__ __forceinline__ float gelu_f(float v) {
    return 0.5f * v * (1.0f + erff(v * 0.7071067811865476f));
}

__device__ __forceinline__ uint32_t f2tf(float x) {
    uint32_t u;
    asm("cvt.rna.tf32.f32 %0, %1;" : "=r"(u) : "f"(x));
    return u;
}

__device__ __forceinline__ void mma_tf32(float (&d)[4], const uint32_t (&a)[4], const uint32_t (&b)[2]) {
    asm volatile(
        "mma.sync.aligned.m16n8k8.row.col.f32.tf32.tf32.f32 "
        "{%0,%1,%2,%3}, {%4,%5,%6,%7}, {%8,%9}, {%0,%1,%2,%3};"
        : "+f"(d[0]), "+f"(d[1]), "+f"(d[2]), "+f"(d[3])
        : "r"(a[0]), "r"(a[1]), "r"(a[2]), "r"(a[3]), "r"(b[0]), "r"(b[1]));
}

// ---------------- ctx mean: deterministic two-stage reduction ----------------
__global__ void k_ctx_a(const float* __restrict__ x) {
    int tid = threadIdx.x;
    int idx0 = blockIdx.x * 256 + tid;   // < 65536
    __shared__ float sm[1024];
    float s[4];
#pragma unroll
    for (int b = 0; b < 4; b++) {
        float acc = 0.f;
        const float* p = x + b * 2097152 + idx0;   // N*T*F = 2^21 per b
#pragma unroll 8
        for (int it = 0; it < 32; it++) acc += p[it * 65536];
        s[b] = acc;
    }
#pragma unroll
    for (int b = 0; b < 4; b++) sm[tid * 4 + b] = s[b];
    __syncthreads();
    // output index o = b*64 + f ; contributors are tids f, f+64, f+128, f+192
    int b = tid >> 6, f = tid & 63;
    float tot = sm[f * 4 + b] + sm[(f + 64) * 4 + b] + sm[(f + 128) * 4 + b] + sm[(f + 192) * 4 + b];
    g_part[blockIdx.x * 256 + tid] = tot;
}

__global__ void k_ctx_b() {
    int tid = threadIdx.x;
    float s = 0.f;
    for (int blk = 0; blk < 256; blk++) s += g_part[blk * 256 + tid];
    g_ctx[tid] = s * (1.0f / 32768.0f);
}

// ---------------- A row-normalize + transpose: g_AnT[k][j][i] ----------------
__global__ void k_normA(const float* __restrict__ A_list) {
    int row = blockIdx.x;          // row = k*256 + i
    int tid = threadIdx.x;         // tid = j
    float v = A_list[row * 256 + tid];
    float s = v;
#pragma unroll
    for (int o = 16; o > 0; o >>= 1) s += __shfl_xor_sync(0xffffffffu, s, o);
    __shared__ float red[8];
    __shared__ float invs;
    if ((tid & 31) == 0) red[tid >> 5] = s;
    __syncthreads();
    if (tid == 0) {
        float t = 0.f;
#pragma unroll
        for (int w = 0; w < 8; w++) t += red[w];
        invs = 1.0f / fmaxf(t, 1e-8f);
    }
    __syncthreads();
    int k = row >> 8, i = row & 255;
    g_AnT[k * 65536 + tid * 256 + i] = v * invs;
}

// ---------------- gate MLP -> alpha[b][k] ----------------
__global__ void k_gate(const float* __restrict__ lag_embed,
                       const float* __restrict__ cw1, const float* __restrict__ cb1,
                       const float* __restrict__ cw2, const float* __restrict__ cb2,
                       const float* __restrict__ gw1, const float* __restrict__ gb1,
                       const float* __restrict__ gw2, const float* __restrict__ gb2) {
    int tid = threadIdx.x;
    if (tid >= 32) return;
    int b = tid >> 3, kk = tid & 7;
    float e1[8];
#pragma unroll
    for (int e = 0; e < 8; e++) {
        float s = cb1[e];
        for (int f = 0; f < 64; f++) s += g_ctx[b * 64 + f] * cw1[f * 8 + e];
        e1[e] = gelu_f(s);
    }
    float cf[8];
#pragma unroll
    for (int e2 = 0; e2 < 8; e2++) {
        float s = cb2[e2];
#pragma unroll
        for (int e = 0; e < 8; e++) s += e1[e] * cw2[e * 8 + e2];
        cf[e2] = s;
    }
    float gg[8];
#pragma unroll
    for (int e = 0; e < 8; e++) {
        float s = gb1[e];
#pragma unroll
        for (int i = 0; i < 16; i++) {
            float gi = (i < 8) ? lag_embed[kk * 8 + i] : cf[i - 8];
            s += gi * gw1[i * 8 + e];
        }
        gg[e] = gelu_f(s);
    }
    float o = gb2[0];
#pragma unroll
    for (int e = 0; e < 8; e++) o += gg[e] * gw2[e];
    g_alpha[b * 8 + kk] = 1.0f / (1.0f + expf(-o));
}

// ---------------- K1: h = x @ in_w + in_b, stored transposed [b][t][n][h] ----
__global__ __launch_bounds__(256) void k_h(const float* __restrict__ x,
                                           const float* __restrict__ in_w,
                                           const float* __restrict__ in_b) {
    __shared__ float xst[32 * 129];   // f-major x tile (chunk of 32 f)
    __shared__ float ws[32 * 128];    // weight tile
    int tid = threadIdx.x;
    int r0 = blockIdx.x * 128;        // row = (b*N + n)*T + t -> tile is fixed (b,n), t = 0..127
    int c0 = blockIdx.y * 128;
    int ty = tid >> 4, tx = tid & 15;
    float acc[8][8];
#pragma unroll
    for (int q = 0; q < 8; q++)
#pragma unroll
        for (int e = 0; e < 8; e++) acc[q][e] = 0.f;

    for (int f0 = 0; f0 < 64; f0 += 32) {
        __syncthreads();
#pragma unroll
        for (int p = 0; p < 16; p++) {
            int idx = tid + p * 256;
            int f = idx >> 7, c = idx & 127;
            ws[f * 128 + c] = in_w[(f0 + f) * 256 + c0 + c];
        }
        int fx = tid & 31, rr0 = tid >> 5;
#pragma unroll
        for (int p = 0; p < 16; p++) {
            int rr = rr0 + p * 8;
            xst[fx * 129 + rr] = x[(r0 + rr) * 64 + f0 + fx];
        }
        __syncthreads();
#pragma unroll
        for (int f = 0; f < 32; f++) {
            float a[8];
#pragma unroll
            for (int q = 0; q < 8; q++) a[q] = xst[f * 129 + ty * 8 + q];
            float4 w0 = *(const float4*)&ws[f * 128 + tx * 4];
            float4 w1 = *(const float4*)&ws[f * 128 + 64 + tx * 4];
#pragma unroll
            for (int q = 0; q < 8; q++) {
                acc[q][0] += a[q] * w0.x;  acc[q][1] += a[q] * w0.y;
                acc[q][2] += a[q] * w0.z;  acc[q][3] += a[q] * w0.w;
                acc[q][4] += a[q] * w1.x;  acc[q][5] += a[q] * w1.y;
                acc[q][6] += a[q] * w1.z;  acc[q][7] += a[q] * w1.w;
            }
        }
    }
    float4 bb0 = *(const float4*)&in_b[c0 + tx * 4];
    float4 bb1 = *(const float4*)&in_b[c0 + 64 + tx * 4];
    int b_ = r0 >> 15, n_ = (r0 >> 7) & 255;
    float* base = g_ht + b_ * (Tn * Nn * Hn) + n_ * Hn;
#pragma unroll
    for (int q = 0; q < 8; q++) {
        int t_ = ty * 8 + q;
        float* o = base + t_ * (Nn * Hn) + c0;
        float4 v0 = make_float4(acc[q][0] + bb0.x, acc[q][1] + bb0.y, acc[q][2] + bb0.z, acc[q][3] + bb0.w);
        float4 v1 = make_float4(acc[q][4] + bb1.x, acc[q][5] + bb1.y, acc[q][6] + bb1.z, acc[q][7] + bb1.w);
        *(float4*)(o + tx * 4) = v0;
        *(float4*)(o + 64 + tx * 4) = v1;
    }
}

// ---------------- K2: agg[b,t] = sum_k alpha[b,k] * An[k] @ h[b,t-k]  (tf32 MMA)
__global__ __launch_bounds__(256, 2) void k_spatial() {
    __shared__ uint32_t As[16 * 132];   // [j-chunk][i]  (tf32 bits)
    __shared__ uint32_t Bs2[16 * 132];  // [j-chunk][h]
    int tid = threadIdx.x, lane = tid & 31, warp = tid >> 5;
    int bt = blockIdx.z, b = bt >> 7, t = bt & 127;
    int i0 = blockIdx.x * 128, h0 = blockIdx.y * 128;
    int wm = warp & 1, wn = warp >> 1;      // warp tile: 64(m) x 32(n)
    int r = lane >> 2, cl = lane & 3;

    float acc[4][4][4];
#pragma unroll
    for (int mt = 0; mt < 4; mt++)
#pragma unroll
        for (int nt = 0; nt < 4; nt++)
#pragma unroll
            for (int e = 0; e < 4; e++) acc[mt][nt][e] = 0.f;

    for (int kk = 0; kk < 8; kk++) {
        int t2 = t - kk;
        if (t2 < 0) break;   // uniform across CTA
        float al = g_alpha[b * 8 + kk];
        const float* Ab = g_AnT + kk * 65536;
        const float* Hb = g_ht + (b * Tn + t2) * (Nn * Hn);
        for (int jj = 0; jj < 256; jj += 16) {
            __syncthreads();
#pragma unroll
            for (int p = 0; p < 8; p++) {
                int idx = tid + p * 256;
                int j = idx >> 7, c = idx & 127;
                As[j * 132 + c]  = f2tf(al * Ab[(jj + j) * 256 + i0 + c]);
                Bs2[j * 132 + c] = f2tf(Hb[(jj + j) * 256 + h0 + c]);
            }
            __syncthreads();
#pragma unroll
            for (int ks = 0; ks < 2; ks++) {
                int ko = ks * 8;
                uint32_t a[4][4], bf[4][2];
#pragma unroll
                for (int mt = 0; mt < 4; mt++) {
                    int rb = wm * 64 + mt * 16 + r;
                    a[mt][0] = As[(ko + cl) * 132 + rb];
                    a[mt][1] = As[(ko + cl) * 132 + rb + 8];
                    a[mt][2] = As[(ko + 4 + cl) * 132 + rb];
                    a[mt][3] = As[(ko + 4 + cl) * 132 + rb + 8];
                }
#pragma unroll
                for (int nt = 0; nt < 4; nt++) {
                    int nb = wn * 32 + nt * 8 + r;
                    bf[nt][0] = Bs2[(ko + cl) * 132 + nb];
                    bf[nt][1] = Bs2[(ko + 4 + cl) * 132 + nb];
                }
#pragma unroll
                for (int mt = 0; mt < 4; mt++)
#pragma unroll
                    for (int nt = 0; nt < 4; nt++)
                        mma_tf32(acc[mt][nt], a[mt], bf[nt]);
            }
        }
    }
    float* Og = g_agg + (b * Tn + t) * (Nn * Hn);
#pragma unroll
    for (int mt = 0; mt < 4; mt++) {
        int rowb = i0 + wm * 64 + mt * 16 + r;
#pragma unroll
        for (int nt = 0; nt < 4; nt++) {
            int col = h0 + wn * 32 + nt * 8 + 2 * cl;
            *(float2*)(Og + rowb * 256 + col)       = make_float2(acc[mt][nt][0], acc[mt][nt][1]);
            *(float2*)(Og + (rowb + 8) * 256 + col) = make_float2(acc[mt][nt][2], acc[mt][nt][3]);
        }
    }
}

// ---------------- K3: out2 = agg@out_w + out_b; res = out2 + h_t; LN; GELU; transpose
__global__ __launch_bounds__(256, 2) void k_out(const float* __restrict__ out_w,
                                                const float* __restrict__ out_b,
                                                const float* __restrict__ ln_g,
                                                const float* __restrict__ ln_b,
                                                float* __restrict__ out) {
    __shared__ float Ast[16 * 68];    // agg tile, j-major
    __shared__ float Bs[16 * 256];    // out_w tile
    int tid = threadIdx.x;
    int r0 = blockIdx.x * 64;         // rows = (b*T + t)*N + i
    int ty = tid >> 4, tx = tid & 15;
    float acc[4][16];
#pragma unroll
    for (int q = 0; q < 4; q++)
#pragma unroll
        for (int e = 0; e < 16; e++) acc[q][e] = 0.f;

    for (int jj = 0; jj < 256; jj += 16) {
        __syncthreads();
        {
            int j = tid & 15, rr0 = tid >> 4;
#pragma unroll
            for (int p = 0; p < 4; p++) {
                int rr = rr0 + p * 16;
                Ast[j * 68 + rr] = g_agg[(r0 + rr) * 256 + jj + j];
            }
        }
#pragma unroll
        for (int p = 0; p < 16; p++) Bs[p * 256 + tid] = out_w[(jj + p) * 256 + tid];
        __syncthreads();
#pragma unroll
        for (int j = 0; j < 16; j++) {
            float av[4];
            *(float4*)av = *(const float4*)&Ast[j * 68 + ty * 4];
#pragma unroll
            for (int cc = 0; cc < 4; cc++) {
                float bv[4];
                *(float4*)bv = *(const float4*)&Bs[j * 256 + cc * 64 + tx * 4];
#pragma unroll
                for (int q = 0; q < 4; q++) {
#pragma unroll
                    for (int e = 0; e < 4; e++) acc[q][cc * 4 + e] += av[q] * bv[e];
                }
            }
        }
    }

#pragma unroll
    for (int q = 0; q < 4; q++) {
        int rg = r0 + ty * 4 + q;
        const float* hrow = g_ht + rg * 256;
        float v[16];
        float s = 0.f, s2 = 0.f;
#pragma unroll
        for (int cc = 0; cc < 4; cc++) {
            float hb[4], ob[4];
            *(float4*)hb = *(const float4*)&hrow[cc * 64 + tx * 4];
            *(float4*)ob = *(const float4*)&out_b[cc * 64 + tx * 4];
#pragma unroll
            for (int e = 0; e < 4; e++) {
                float val = acc[q][cc * 4 + e] + ob[e] + hb[e];
                v[cc * 4 + e] = val;
                s += val;
                s2 += val * val;
            }
        }
        // reduce across the 16 threads (half-warp) that own this row
#pragma unroll
        for (int o = 8; o > 0; o >>= 1) {
            s  += __shfl_xor_sync(0xffffffffu, s, o);
            s2 += __shfl_xor_sync(0xffffffffu, s2, o);
        }
        float mu = s * (1.0f / 256.0f);
        float var = s2 * (1.0f / 256.0f) - mu * mu;
        float rs = rsqrtf(var + 1e-5f);
        int b_ = rg >> 15, t_ = (rg >> 8) & 127, n_ = rg & 255;
        float* orow = out + ((b_ * 256 + n_) * 128 + t_) * 256;
#pragma unroll
        for (int cc = 0; cc < 4; cc++) {
            float lg[4], lb[4], ov[4];
            *(float4*)lg = *(const float4*)&ln_g[cc * 64 + tx * 4];
            *(float4*)lb = *(const float4*)&ln_b[cc * 64 + tx * 4];
#pragma unroll
            for (int e = 0; e < 4; e++) {
                float z = (v[cc * 4 + e] - mu) * rs * lg[e] + lb[e];
                ov[e] = gelu_f(z);
            }
            *(float4*)&orow[cc * 64 + tx * 4] = *(float4*)ov;
        }
    }
}

extern "C" void kernel_launch(void* const* d_in, const int* in_sizes, int n_in,
                              void* d_out, int out_size) {
    const float* x       = (const float*)d_in[0];
    const float* A_list  = (const float*)d_in[1];
    const float* in_w    = (const float*)d_in[2];
    const float* in_b    = (const float*)d_in[3];
    const float* out_w   = (const float*)d_in[4];
    const float* out_b   = (const float*)d_in[5];
    const float* lag     = (const float*)d_in[6];
    const float* cw1     = (const float*)d_in[7];
    const float* cb1     = (const float*)d_in[8];
    const float* cw2     = (const float*)d_in[9];
    const float* cb2     = (const float*)d_in[10];
    const float* gw1     = (const float*)d_in[11];
    const float* gb1     = (const float*)d_in[12];
    const float* gw2     = (const float*)d_in[13];
    const float* gb2     = (const float*)d_in[14];
    const float* lng     = (const float*)d_in[15];
    const float* lnb     = (const float*)d_in[16];
    float* out = (float*)d_out;

    k_ctx_a<<<256, 256>>>(x);
    k_ctx_b<<<1, 256>>>();
    k_normA<<<2048, 256>>>(A_list);
    k_gate<<<1, 32>>>(lag, cw1, cb1, cw2, cb2, gw1, gb1, gw2, gb2);
    k_h<<<dim3(1024, 2), 256>>>(x, in_w, in_b);
    k_spatial<<<dim3(2, 2, 512), 256>>>();
    k_out<<<2048, 256>>>(out_w, out_b, lng, lnb, out);
}

// round 5
// speedup vs baseline: 1.8874x; 1.8874x over previous
#include <cuda_runtime.h>
#include <cuda_bf16.h>
#include <cstdint>
#include <math.h>

#define Bn 4
#define Nn 256
#define Tn 128
#define Fn 64
#define Kn 8
#define Hn 256

// ---------------- scratch (static device globals) ----------------
__device__ float g_ht[Bn*Tn*Nn*Hn];            // h transposed: [b][t][n][h] fp32
__device__ float g_agg[Bn*Tn*Nn*Hn];           // lag-graph aggregate: [b][t][i][h] fp32
__device__ float g_An[Kn*Nn*Nn];               // normalized A: [k][i][j] fp32
__device__ __nv_bfloat16 g_AbfS[Bn*Kn*Nn*Nn];  // alpha-scaled A bf16: [b][k][i][j]
__device__ __nv_bfloat16 g_hbfT[Bn*Tn*Hn*Nn];  // h bf16 transposed: [b][t][h][n]
__device__ float g_part[256*256];              // ctx partial sums
__device__ float g_alpha[Bn*Kn];               // gate values

__device__ __forceinline__ float gelu_f(float v) {
    return 0.5f * v * (1.0f + erff(v * 0.7071067811865476f));
}

__device__ __forceinline__ uint32_t f2tf(float x) {
    uint32_t u;
    asm("cvt.rna.tf32.f32 %0, %1;" : "=r"(u) : "f"(x));
    return u;
}

__device__ __forceinline__ void mma_tf32(float (&d)[4], const uint32_t (&a)[4], const uint32_t (&b)[2]) {
    asm volatile(
        "mma.sync.aligned.m16n8k8.row.col.f32.tf32.tf32.f32 "
        "{%0,%1,%2,%3}, {%4,%5,%6,%7}, {%8,%9}, {%0,%1,%2,%3};"
        : "+f"(d[0]), "+f"(d[1]), "+f"(d[2]), "+f"(d[3])
        : "r"(a[0]), "r"(a[1]), "r"(a[2]), "r"(a[3]), "r"(b[0]), "r"(b[1]));
}

__device__ __forceinline__ void mma_bf16(float (&d)[4], const uint32_t (&a)[4], const uint32_t (&b)[2]) {
    asm volatile(
        "mma.sync.aligned.m16n8k16.row.col.f32.bf16.bf16.f32 "
        "{%0,%1,%2,%3}, {%4,%5,%6,%7}, {%8,%9}, {%0,%1,%2,%3};"
        : "+f"(d[0]), "+f"(d[1]), "+f"(d[2]), "+f"(d[3])
        : "r"(a[0]), "r"(a[1]), "r"(a[2]), "r"(a[3]), "r"(b[0]), "r"(b[1]));
}

__device__ __forceinline__ void ldsm_x4(uint32_t (&r)[4], uint32_t addr) {
    asm volatile("ldmatrix.sync.aligned.m8n8.x4.shared.b16 {%0,%1,%2,%3}, [%4];"
                 : "=r"(r[0]), "=r"(r[1]), "=r"(r[2]), "=r"(r[3]) : "r"(addr));
}

__device__ __forceinline__ uint32_t smem_u32(const void* p) {
    uint32_t a;
    asm("{ .reg .u64 t; cvta.to.shared.u64 t, %1; cvt.u32.u64 %0, t; }" : "=r"(a) : "l"(p));
    return a;
}

__device__ __forceinline__ void cp_async16(uint32_t dst, const void* src) {
    asm volatile("cp.async.cg.shared.global [%0], [%1], 16;" :: "r"(dst), "l"(src));
}

// ---------------- ctx mean stage 1 ----------------
__global__ void k_ctx_a(const float* __restrict__ x) {
    int tid = threadIdx.x;
    int idx0 = blockIdx.x * 256 + tid;
    __shared__ float sm[1024];
    float s[4];
#pragma unroll
    for (int b = 0; b < 4; b++) {
        float acc = 0.f;
        const float* p = x + b * 2097152 + idx0;
#pragma unroll 8
        for (int it = 0; it < 32; it++) acc += p[it * 65536];
        s[b] = acc;
    }
#pragma unroll
    for (int b = 0; b < 4; b++) sm[tid * 4 + b] = s[b];
    __syncthreads();
    int b = tid >> 6, f = tid & 63;
    float tot = sm[f * 4 + b] + sm[(f + 64) * 4 + b] + sm[(f + 128) * 4 + b] + sm[(f + 192) * 4 + b];
    g_part[blockIdx.x * 256 + tid] = tot;
}

// ---------------- A row-normalize: g_An[k][i][j] ----------------
__global__ void k_normA(const float* __restrict__ A_list) {
    int row = blockIdx.x;          // row = k*256 + i
    int tid = threadIdx.x;         // j
    float v = A_list[row * 256 + tid];
    float s = v;
#pragma unroll
    for (int o = 16; o > 0; o >>= 1) s += __shfl_xor_sync(0xffffffffu, s, o);
    __shared__ float red[8];
    __shared__ float invs;
    if ((tid & 31) == 0) red[tid >> 5] = s;
    __syncthreads();
    if (tid == 0) {
        float t = 0.f;
#pragma unroll
        for (int w = 0; w < 8; w++) t += red[w];
        invs = 1.0f / fmaxf(t, 1e-8f);
    }
    __syncthreads();
    g_An[row * 256 + tid] = v * invs;
}

// ---------------- ctx stage 2 + gate MLP fused -> alpha ----------------
__global__ void k_gate(const float* __restrict__ lag_embed,
                       const float* __restrict__ cw1, const float* __restrict__ cb1,
                       const float* __restrict__ cw2, const float* __restrict__ cb2,
                       const float* __restrict__ gw1, const float* __restrict__ gb1,
                       const float* __restrict__ gw2, const float* __restrict__ gb2) {
    __shared__ float ctx_sm[256];
    int tid = threadIdx.x;
    float s = 0.f;
    for (int blk = 0; blk < 256; blk++) s += g_part[blk * 256 + tid];
    ctx_sm[tid] = s * (1.0f / 32768.0f);
    __syncthreads();
    if (tid >= 32) return;
    int b = tid >> 3, kk = tid & 7;
    float e1[8];
#pragma unroll
    for (int e = 0; e < 8; e++) {
        float t = cb1[e];
        for (int f = 0; f < 64; f++) t += ctx_sm[b * 64 + f] * cw1[f * 8 + e];
        e1[e] = gelu_f(t);
    }
    float cf[8];
#pragma unroll
    for (int e2 = 0; e2 < 8; e2++) {
        float t = cb2[e2];
#pragma unroll
        for (int e = 0; e < 8; e++) t += e1[e] * cw2[e * 8 + e2];
        cf[e2] = t;
    }
    float gg[8];
#pragma unroll
    for (int e = 0; e < 8; e++) {
        float t = gb1[e];
#pragma unroll
        for (int i = 0; i < 16; i++) {
            float gi = (i < 8) ? lag_embed[kk * 8 + i] : cf[i - 8];
            t += gi * gw1[i * 8 + e];
        }
        gg[e] = gelu_f(t);
    }
    float o = gb2[0];
#pragma unroll
    for (int e = 0; e < 8; e++) o += gg[e] * gw2[e];
    g_alpha[b * 8 + kk] = 1.0f / (1.0f + expf(-o));
}

// ---------------- scale A by alpha, cast bf16: g_AbfS[b][k][i][j] ----------------
__global__ void k_scaleA() {
    int row = blockIdx.x;          // k*256 + i
    int j = threadIdx.x;
    int k = row >> 8;
    float a = g_An[row * 256 + j];
#pragma unroll
    for (int b = 0; b < 4; b++) {
        float al = g_alpha[b * 8 + k];
        g_AbfS[((size_t)(b * 8 + k) * 256 + (row & 255)) * 256 + j] = __float2bfloat16(al * a);
    }
}

// ---------------- K1: h = x @ in_w + in_b, stored [b][t][n][h] fp32 ----------------
__global__ __launch_bounds__(256) void k_h(const float* __restrict__ x,
                                           const float* __restrict__ in_w,
                                           const float* __restrict__ in_b) {
    __shared__ float xst[32 * 129];
    __shared__ float ws[32 * 128];
    int tid = threadIdx.x;
    int r0 = blockIdx.x * 128;        // fixed (b,n), t = 0..127
    int c0 = blockIdx.y * 128;
    int ty = tid >> 4, tx = tid & 15;
    float acc[8][8];
#pragma unroll
    for (int q = 0; q < 8; q++)
#pragma unroll
        for (int e = 0; e < 8; e++) acc[q][e] = 0.f;

    for (int f0 = 0; f0 < 64; f0 += 32) {
        __syncthreads();
#pragma unroll
        for (int p = 0; p < 16; p++) {
            int idx = tid + p * 256;
            int f = idx >> 7, c = idx & 127;
            ws[f * 128 + c] = in_w[(f0 + f) * 256 + c0 + c];
        }
        int fx = tid & 31, rr0 = tid >> 5;
#pragma unroll
        for (int p = 0; p < 16; p++) {
            int rr = rr0 + p * 8;
            xst[fx * 129 + rr] = x[(r0 + rr) * 64 + f0 + fx];
        }
        __syncthreads();
#pragma unroll
        for (int f = 0; f < 32; f++) {
            float a[8];
#pragma unroll
            for (int q = 0; q < 8; q++) a[q] = xst[f * 129 + ty * 8 + q];
            float4 w0 = *(const float4*)&ws[f * 128 + tx * 4];
            float4 w1 = *(const float4*)&ws[f * 128 + 64 + tx * 4];
#pragma unroll
            for (int q = 0; q < 8; q++) {
                acc[q][0] += a[q] * w0.x;  acc[q][1] += a[q] * w0.y;
                acc[q][2] += a[q] * w0.z;  acc[q][3] += a[q] * w0.w;
                acc[q][4] += a[q] * w1.x;  acc[q][5] += a[q] * w1.y;
                acc[q][6] += a[q] * w1.z;  acc[q][7] += a[q] * w1.w;
            }
        }
    }
    float4 bb0 = *(const float4*)&in_b[c0 + tx * 4];
    float4 bb1 = *(const float4*)&in_b[c0 + 64 + tx * 4];
    int b_ = r0 >> 15, n_ = (r0 >> 7) & 255;
    float* base = g_ht + (size_t)b_ * (Tn * Nn * Hn) + n_ * Hn;
#pragma unroll
    for (int q = 0; q < 8; q++) {
        int t_ = ty * 8 + q;
        float* o = base + (size_t)t_ * (Nn * Hn) + c0;
        float4 v0 = make_float4(acc[q][0] + bb0.x, acc[q][1] + bb0.y, acc[q][2] + bb0.z, acc[q][3] + bb0.w);
        float4 v1 = make_float4(acc[q][4] + bb1.x, acc[q][5] + bb1.y, acc[q][6] + bb1.z, acc[q][7] + bb1.w);
        *(float4*)(o + tx * 4) = v0;
        *(float4*)(o + 64 + tx * 4) = v1;
    }
}

// ---------------- transpose h -> bf16 [b][t][h][n] ----------------
__global__ void k_trans() {
    __shared__ float tile[32][33];
    int bt = blockIdx.z;
    int n0 = blockIdx.x * 32, h0 = blockIdx.y * 32;
    int tx = threadIdx.x, ty = threadIdx.y;
    const float* src = g_ht + (size_t)bt * 65536;
    __nv_bfloat16* dst = g_hbfT + (size_t)bt * 65536;
#pragma unroll
    for (int p = 0; p < 4; p++)
        tile[ty + p * 8][tx] = src[(n0 + ty + p * 8) * 256 + h0 + tx];
    __syncthreads();
#pragma unroll
    for (int p = 0; p < 4; p++)
        dst[(h0 + ty + p * 8) * 256 + n0 + tx] = __float2bfloat16(tile[tx][ty + p * 8]);
}

// ---------------- K2: bf16 mma.sync GEMM, double-buffered cp.async ----------------
// out[b,t][i][h] = sum_lag sum_j (alpha*An)[b,lag][i][j] * h[b][t-lag][j][h]
// CTA tile 128(i) x 128(h); K chunks of 32 over (lag, j).
// A smem: [128 i][32 j] bf16, pitch 80B.  B smem: [128 h][32 j] bf16, pitch 80B.
#define PITCH 80
__global__ __launch_bounds__(256, 2) void k_spatial_bf16() {
    __shared__ __align__(16) char sA[2][128 * PITCH];
    __shared__ __align__(16) char sB[2][128 * PITCH];
    int tid = threadIdx.x, lane = tid & 31, warp = tid >> 5;
    int i0 = blockIdx.x * 128, h0 = blockIdx.y * 128;
    int bt = blockIdx.z, b = bt >> 7, t = bt & 127;
    int wm = warp & 1, wn = warp >> 1;    // warp tile 64(m) x 32(n)

    float acc[4][4][4];
#pragma unroll
    for (int mt = 0; mt < 4; mt++)
#pragma unroll
        for (int nt = 0; nt < 4; nt++)
#pragma unroll
            for (int e = 0; e < 4; e++) acc[mt][nt][e] = 0.f;

    int nlag = (t + 1 < 8) ? (t + 1) : 8;
    int nch = nlag * 8;

    const char* Ab = (const char*)g_AbfS + (size_t)b * 8 * 131072 + (size_t)i0 * 512;
    const char* Hb = (const char*)g_hbfT + ((size_t)(b * 128 + t)) * 131072 + (size_t)h0 * 512;

    uint32_t sAb[2] = { smem_u32(sA[0]), smem_u32(sA[1]) };
    uint32_t sBb[2] = { smem_u32(sB[0]), smem_u32(sB[1]) };

    int lrow = tid >> 2, lc = (tid & 3) * 16;        // loader: 2 passes x (64 rows)
    int lbyte0 = lrow * PITCH + lc;
    int gbyte0 = lrow * 512 + lc;

    // issue loads for chunk c into buffer s
    auto issue = [&](int c, int s) {
        int lag = c >> 3, j0b = (c & 7) * 64;
        const char* asrc = Ab + (size_t)lag * 131072 + j0b;
        const char* bsrc = Hb - (size_t)lag * 131072 + j0b;
        cp_async16(sAb[s] + lbyte0, asrc + gbyte0);
        cp_async16(sAb[s] + lbyte0 + 64 * PITCH, asrc + gbyte0 + 64 * 512);
        cp_async16(sBb[s] + lbyte0, bsrc + gbyte0);
        cp_async16(sBb[s] + lbyte0 + 64 * PITCH, bsrc + gbyte0 + 64 * 512);
        asm volatile("cp.async.commit_group;" ::: "memory");
    };

    issue(0, 0);
    issue(1, 1);

    // fragment load offsets (bytes) within a buffer
    int arow = wm * 64 + (lane & 15);
    int akoff = (lane >> 4) * 8;                     // halves
    int brow = wn * 32 + (lane & 7) + (lane >> 4) * 8;
    int bkoff = ((lane >> 3) & 1) * 8;

    for (int c = 0; c < nch; ++c) {
        int s = c & 1;
        if (c == nch - 1) asm volatile("cp.async.wait_group 0;" ::: "memory");
        else              asm volatile("cp.async.wait_group 1;" ::: "memory");
        __syncthreads();
#pragma unroll
        for (int ks = 0; ks < 2; ks++) {
            uint32_t a[4][4];
#pragma unroll
            for (int mt = 0; mt < 4; mt++)
                ldsm_x4(a[mt], sAb[s] + (arow + mt * 16) * PITCH + (ks * 16 + akoff) * 2);
            uint32_t bb[2][4];
#pragma unroll
            for (int np = 0; np < 2; np++)
                ldsm_x4(bb[np], sBb[s] + (brow + np * 16) * PITCH + (ks * 16 + bkoff) * 2);
#pragma unroll
            for (int mt = 0; mt < 4; mt++)
#pragma unroll
                for (int nt = 0; nt < 4; nt++) {
                    uint32_t bfr[2] = { bb[nt >> 1][(nt & 1) * 2], bb[nt >> 1][(nt & 1) * 2 + 1] };
                    mma_bf16(acc[mt][nt], a[mt], bfr);
                }
        }
        __syncthreads();
        if (c + 2 < nch) issue(c + 2, s);
    }

    int r = lane >> 2, cl = lane & 3;
    float* Og = g_agg + (size_t)bt * 65536;
#pragma unroll
    for (int mt = 0; mt < 4; mt++) {
        int row = i0 + wm * 64 + mt * 16 + r;
#pragma unroll
        for (int nt = 0; nt < 4; nt++) {
            int col = h0 + wn * 32 + nt * 8 + 2 * cl;
            *(float2*)(Og + (size_t)row * 256 + col)       = make_float2(acc[mt][nt][0], acc[mt][nt][1]);
            *(float2*)(Og + (size_t)(row + 8) * 256 + col) = make_float2(acc[mt][nt][2], acc[mt][nt][3]);
        }
    }
}

// ---------------- K3: out2 = agg@out_w + out_b; +h; LN; GELU; transpose (tf32 mma)
__global__ __launch_bounds__(256) void k_out_tc(const float* __restrict__ out_w,
                                                const float* __restrict__ out_b,
                                                const float* __restrict__ ln_g,
                                                const float* __restrict__ ln_b,
                                                float* __restrict__ out) {
    __shared__ uint32_t As[16 * 68];
    __shared__ uint32_t Bs[16 * 260];
    __shared__ float red[64 * 8];   // [row][wn][s/s2]
    int tid = threadIdx.x, lane = tid & 31, warp = tid >> 5;
    int r0 = blockIdx.x * 64;       // rows = (b*T + t)*N + n
    int wm = warp & 1, wn = warp >> 1;
    int r = lane >> 2, cl = lane & 3;

    float acc[2][8][4];
#pragma unroll
    for (int mt = 0; mt < 2; mt++)
#pragma unroll
        for (int nt = 0; nt < 8; nt++)
#pragma unroll
            for (int e = 0; e < 4; e++) acc[mt][nt][e] = 0.f;

    for (int kk = 0; kk < 256; kk += 16) {
        __syncthreads();
#pragma unroll
        for (int p = 0; p < 4; p++) {
            int idx = tid + p * 256;
            int row = idx >> 4, k = idx & 15;
            As[k * 68 + row] = f2tf(g_agg[(size_t)(r0 + row) * 256 + kk + k]);
        }
#pragma unroll
        for (int p = 0; p < 16; p++) {
            int idx = tid + p * 256;
            int k = idx >> 8, col = idx & 255;
            Bs[k * 260 + col] = f2tf(out_w[(kk + k) * 256 + col]);
        }
        __syncthreads();
#pragma unroll
        for (int ks = 0; ks < 2; ks++) {
            int ko = ks * 8;
            uint32_t a[2][4], bfr[8][2];
#pragma unroll
            for (int mt = 0; mt < 2; mt++) {
                int rb = wm * 32 + mt * 16 + r;
                a[mt][0] = As[(ko + cl) * 68 + rb];
                a[mt][1] = As[(ko + cl) * 68 + rb + 8];
                a[mt][2] = As[(ko + 4 + cl) * 68 + rb];
                a[mt][3] = As[(ko + 4 + cl) * 68 + rb + 8];
            }
#pragma unroll
            for (int nt = 0; nt < 8; nt++) {
                int nb = wn * 64 + nt * 8 + r;
                bfr[nt][0] = Bs[(ko + cl) * 260 + nb];
                bfr[nt][1] = Bs[(ko + 4 + cl) * 260 + nb];
            }
#pragma unroll
            for (int mt = 0; mt < 2; mt++)
#pragma unroll
                for (int nt = 0; nt < 8; nt++)
                    mma_tf32(acc[mt][nt], a[mt], bfr[nt]);
        }
    }

    // epilogue: residual + LN stats
#pragma unroll
    for (int mt = 0; mt < 2; mt++) {
#pragma unroll
        for (int rr = 0; rr < 2; rr++) {
            int row_local = wm * 32 + mt * 16 + rr * 8 + r;
            size_t rg = (size_t)r0 + row_local;
            const float* hrow = g_ht + rg * 256;
            float ss = 0.f, ss2 = 0.f;
#pragma unroll
            for (int nt = 0; nt < 8; nt++) {
                int col = wn * 64 + nt * 8 + 2 * cl;
                float2 hb = *(const float2*)&hrow[col];
                float2 ob = *(const float2*)&out_b[col];
                float v0 = acc[mt][nt][rr * 2 + 0] + ob.x + hb.x;
                float v1 = acc[mt][nt][rr * 2 + 1] + ob.y + hb.y;
                acc[mt][nt][rr * 2 + 0] = v0;
                acc[mt][nt][rr * 2 + 1] = v1;
                ss += v0 + v1;
                ss2 += v0 * v0 + v1 * v1;
            }
            ss += __shfl_xor_sync(0xffffffffu, ss, 1);
            ss2 += __shfl_xor_sync(0xffffffffu, ss2, 1);
            ss += __shfl_xor_sync(0xffffffffu, ss, 2);
            ss2 += __shfl_xor_sync(0xffffffffu, ss2, 2);
            if (cl == 0) {
                red[row_local * 8 + wn * 2 + 0] = ss;
                red[row_local * 8 + wn * 2 + 1] = ss2;
            }
        }
    }
    __syncthreads();
#pragma unroll
    for (int mt = 0; mt < 2; mt++) {
#pragma unroll
        for (int rr = 0; rr < 2; rr++) {
            int row_local = wm * 32 + mt * 16 + rr * 8 + r;
            float ts = 0.f, ts2 = 0.f;
#pragma unroll
            for (int w2 = 0; w2 < 4; w2++) {
                ts += red[row_local * 8 + w2 * 2 + 0];
                ts2 += red[row_local * 8 + w2 * 2 + 1];
            }
            float mu = ts * (1.0f / 256.0f);
            float var = ts2 * (1.0f / 256.0f) - mu * mu;
            float rs = rsqrtf(var + 1e-5f);
            int rg = r0 + row_local;
            int b_ = rg >> 15, t_ = (rg >> 8) & 127, n_ = rg & 255;
            float* orow = out + (((size_t)b_ * 256 + n_) * 128 + t_) * 256;
#pragma unroll
            for (int nt = 0; nt < 8; nt++) {
                int col = wn * 64 + nt * 8 + 2 * cl;
                float2 lg = *(const float2*)&ln_g[col];
                float2 lb = *(const float2*)&ln_b[col];
                float z0 = (acc[mt][nt][rr * 2 + 0] - mu) * rs * lg.x + lb.x;
                float z1 = (acc[mt][nt][rr * 2 + 1] - mu) * rs * lg.y + lb.y;
                *(float2*)&orow[col] = make_float2(gelu_f(z0), gelu_f(z1));
            }
        }
    }
}

extern "C" void kernel_launch(void* const* d_in, const int* in_sizes, int n_in,
                              void* d_out, int out_size) {
    const float* x       = (const float*)d_in[0];
    const float* A_list  = (const float*)d_in[1];
    const float* in_w    = (const float*)d_in[2];
    const float* in_b    = (const float*)d_in[3];
    const float* out_w   = (const float*)d_in[4];
    const float* out_b   = (const float*)d_in[5];
    const float* lag     = (const float*)d_in[6];
    const float* cw1     = (const float*)d_in[7];
    const float* cb1     = (const float*)d_in[8];
    const float* cw2     = (const float*)d_in[9];
    const float* cb2     = (const float*)d_in[10];
    const float* gw1     = (const float*)d_in[11];
    const float* gb1     = (const float*)d_in[12];
    const float* gw2     = (const float*)d_in[13];
    const float* gb2     = (const float*)d_in[14];
    const float* lng     = (const float*)d_in[15];
    const float* lnb     = (const float*)d_in[16];
    float* out = (float*)d_out;

    k_ctx_a<<<256, 256>>>(x);
    k_normA<<<2048, 256>>>(A_list);
    k_gate<<<1, 256>>>(lag, cw1, cb1, cw2, cb2, gw1, gb1, gw2, gb2);
    k_scaleA<<<2048, 256>>>();
    k_h<<<dim3(1024, 2), 256>>>(x, in_w, in_b);
    k_trans<<<dim3(8, 8, 512), dim3(32, 8)>>>();
    k_spatial_bf16<<<dim3(2, 2, 512), 256>>>();
    k_out_tc<<<2048, 256>>>(out_w, out_b, lng, lnb, out);
}

// round 6
// speedup vs baseline: 2.1914x; 1.1611x over previous
#include <cuda_runtime.h>
#include <cuda_bf16.h>
#include <cstdint>
#include <math.h>

#define Bn 4
#define Nn 256
#define Tn 128
#define Fn 64
#define Kn 8
#define Hn 256

// ---------------- scratch (static device globals) ----------------
__device__ float g_ht[Bn*Tn*Nn*Hn];            // h: [b][t][n][h] fp32
__device__ float g_agg[Bn*Tn*Nn*Hn];           // lag aggregate: [b][t][i][h] fp32
__device__ float g_An[Kn*Nn*Nn];               // normalized A: [k][i][j] fp32
__device__ __nv_bfloat16 g_AbfS[Bn*Kn*Nn*Nn];  // alpha-scaled A bf16: [b][k][i][j]
__device__ __nv_bfloat16 g_hbfT[Bn*Tn*Hn*Nn];  // h bf16 transposed: [b][t][h][n]
__device__ float g_part[256*256];              // ctx partial sums
__device__ float g_alpha[Bn*Kn];               // gate values

__device__ __forceinline__ float gelu_f(float v) {
    return 0.5f * v * (1.0f + erff(v * 0.7071067811865476f));
}

__device__ __forceinline__ uint32_t f2tf(float x) {
    uint32_t u;
    asm("cvt.rna.tf32.f32 %0, %1;" : "=r"(u) : "f"(x));
    return u;
}

__device__ __forceinline__ void mma_tf32(float (&d)[4], const uint32_t (&a)[4], const uint32_t (&b)[2]) {
    asm volatile(
        "mma.sync.aligned.m16n8k8.row.col.f32.tf32.tf32.f32 "
        "{%0,%1,%2,%3}, {%4,%5,%6,%7}, {%8,%9}, {%0,%1,%2,%3};"
        : "+f"(d[0]), "+f"(d[1]), "+f"(d[2]), "+f"(d[3])
        : "r"(a[0]), "r"(a[1]), "r"(a[2]), "r"(a[3]), "r"(b[0]), "r"(b[1]));
}

__device__ __forceinline__ void mma_bf16(float (&d)[4], const uint32_t (&a)[4], const uint32_t (&b)[2]) {
    asm volatile(
        "mma.sync.aligned.m16n8k16.row.col.f32.bf16.bf16.f32 "
        "{%0,%1,%2,%3}, {%4,%5,%6,%7}, {%8,%9}, {%0,%1,%2,%3};"
        : "+f"(d[0]), "+f"(d[1]), "+f"(d[2]), "+f"(d[3])
        : "r"(a[0]), "r"(a[1]), "r"(a[2]), "r"(a[3]), "r"(b[0]), "r"(b[1]));
}

__device__ __forceinline__ void ldsm_x4(uint32_t (&r)[4], uint32_t addr) {
    asm volatile("ldmatrix.sync.aligned.m8n8.x4.shared.b16 {%0,%1,%2,%3}, [%4];"
                 : "=r"(r[0]), "=r"(r[1]), "=r"(r[2]), "=r"(r[3]) : "r"(addr));
}

__device__ __forceinline__ uint32_t smem_u32(const void* p) {
    uint32_t a;
    asm("{ .reg .u64 t; cvta.to.shared.u64 t, %1; cvt.u32.u64 %0, t; }" : "=r"(a) : "l"(p));
    return a;
}

__device__ __forceinline__ void cp_async16(uint32_t dst, const void* src) {
    asm volatile("cp.async.cg.shared.global [%0], [%1], 16;" :: "r"(dst), "l"(src));
}

// swizzled byte offset within a [row][32 bf16] tile, rows 64B, 16B-chunk rotation
// cb must be a multiple of 16.
#define SWC(r, cb) (((r) << 6) + ((((((cb) >> 4) + (((r) >> 1) & 3))) & 3) << 4))

// ---------------- ctx mean stage 1 ----------------
__global__ void k_ctx_a(const float* __restrict__ x) {
    int tid = threadIdx.x;
    int idx0 = blockIdx.x * 256 + tid;
    __shared__ float sm[1024];
    float s[4];
#pragma unroll
    for (int b = 0; b < 4; b++) {
        float acc = 0.f;
        const float* p = x + b * 2097152 + idx0;
#pragma unroll 8
        for (int it = 0; it < 32; it++) acc += p[it * 65536];
        s[b] = acc;
    }
#pragma unroll
    for (int b = 0; b < 4; b++) sm[tid * 4 + b] = s[b];
    __syncthreads();
    int b = tid >> 6, f = tid & 63;
    float tot = sm[f * 4 + b] + sm[(f + 64) * 4 + b] + sm[(f + 128) * 4 + b] + sm[(f + 192) * 4 + b];
    g_part[blockIdx.x * 256 + tid] = tot;
}

// ---------------- A row-normalize: g_An[k][i][j] ----------------
__global__ void k_normA(const float* __restrict__ A_list) {
    int row = blockIdx.x;          // row = k*256 + i
    int tid = threadIdx.x;         // j
    float v = A_list[row * 256 + tid];
    float s = v;
#pragma unroll
    for (int o = 16; o > 0; o >>= 1) s += __shfl_xor_sync(0xffffffffu, s, o);
    __shared__ float red[8];
    __shared__ float invs;
    if ((tid & 31) == 0) red[tid >> 5] = s;
    __syncthreads();
    if (tid == 0) {
        float t = 0.f;
#pragma unroll
        for (int w = 0; w < 8; w++) t += red[w];
        invs = 1.0f / fmaxf(t, 1e-8f);
    }
    __syncthreads();
    g_An[row * 256 + tid] = v * invs;
}

// ---------------- ctx stage 2 + gate MLP fused -> alpha ----------------
__global__ void k_gate(const float* __restrict__ lag_embed,
                       const float* __restrict__ cw1, const float* __restrict__ cb1,
                       const float* __restrict__ cw2, const float* __restrict__ cb2,
                       const float* __restrict__ gw1, const float* __restrict__ gb1,
                       const float* __restrict__ gw2, const float* __restrict__ gb2) {
    __shared__ float ctx_sm[256];
    int tid = threadIdx.x;
    float s = 0.f;
    for (int blk = 0; blk < 256; blk++) s += g_part[blk * 256 + tid];
    ctx_sm[tid] = s * (1.0f / 32768.0f);
    __syncthreads();
    if (tid >= 32) return;
    int b = tid >> 3, kk = tid & 7;
    float e1[8];
#pragma unroll
    for (int e = 0; e < 8; e++) {
        float t = cb1[e];
        for (int f = 0; f < 64; f++) t += ctx_sm[b * 64 + f] * cw1[f * 8 + e];
        e1[e] = gelu_f(t);
    }
    float cf[8];
#pragma unroll
    for (int e2 = 0; e2 < 8; e2++) {
        float t = cb2[e2];
#pragma unroll
        for (int e = 0; e < 8; e++) t += e1[e] * cw2[e * 8 + e2];
        cf[e2] = t;
    }
    float gg[8];
#pragma unroll
    for (int e = 0; e < 8; e++) {
        float t = gb1[e];
#pragma unroll
        for (int i = 0; i < 16; i++) {
            float gi = (i < 8) ? lag_embed[kk * 8 + i] : cf[i - 8];
            t += gi * gw1[i * 8 + e];
        }
        gg[e] = gelu_f(t);
    }
    float o = gb2[0];
#pragma unroll
    for (int e = 0; e < 8; e++) o += gg[e] * gw2[e];
    g_alpha[b * 8 + kk] = 1.0f / (1.0f + expf(-o));
}

// ---------------- scale A by alpha, cast bf16: g_AbfS[b][k][i][j] ----------------
__global__ void k_scaleA() {
    int row = blockIdx.x;          // k*256 + i
    int j = threadIdx.x;
    int k = row >> 8;
    float a = g_An[row * 256 + j];
#pragma unroll
    for (int b = 0; b < 4; b++) {
        float al = g_alpha[b * 8 + k];
        g_AbfS[((size_t)(b * 8 + k) * 256 + (row & 255)) * 256 + j] = __float2bfloat16(al * a);
    }
}

// ---------------- K1: h = x@in_w + in_b (tf32 mma), write g_ht fp32 + g_hbfT bf16^T
union SmemH {
    struct { uint32_t As[32 * 132]; uint32_t Bs[32 * 132]; } g;
    __nv_bfloat16 tr[128 * 136];
};

__global__ __launch_bounds__(256) void k_h2(const float* __restrict__ x,
                                            const float* __restrict__ in_w,
                                            const float* __restrict__ in_b) {
    __shared__ SmemH sm;
    int tid = threadIdx.x, lane = tid & 31, warp = tid >> 5;
    int n0 = blockIdx.x * 128, h0 = blockIdx.y * 128;
    int bt = blockIdx.z, b = bt >> 7, t = bt & 127;
    int wm = warp & 1, wn = warp >> 1;     // warp tile 64(n-rows) x 32(h-cols)
    int r = lane >> 2, cl = lane & 3;

    float acc[4][4][4];
#pragma unroll
    for (int mt = 0; mt < 4; mt++)
#pragma unroll
        for (int nt = 0; nt < 4; nt++)
#pragma unroll
            for (int e = 0; e < 4; e++) acc[mt][nt][e] = 0.f;

    for (int f0 = 0; f0 < 64; f0 += 32) {
        __syncthreads();
        {   // x tile -> As[f][n] (tf32)
            int f = tid & 31, nb = tid >> 5;
            const float* xb = x + (((size_t)(b * 256 + n0) * 128 + t) * 64) + f0 + f;
#pragma unroll
            for (int p = 0; p < 16; p++) {
                int nn = nb + p * 8;
                sm.g.As[f * 132 + nn] = f2tf(xb[(size_t)nn * 8192]);
            }
        }
        {   // w tile -> Bs[f][h] (tf32)
#pragma unroll
            for (int p = 0; p < 16; p++) {
                int idx = tid + p * 256;
                int f = idx >> 7, c = idx & 127;
                sm.g.Bs[f * 132 + c] = f2tf(in_w[(f0 + f) * 256 + h0 + c]);
            }
        }
        __syncthreads();
#pragma unroll
        for (int ks = 0; ks < 4; ks++) {
            int ko = ks * 8;
            uint32_t a[4][4], bfr[4][2];
#pragma unroll
            for (int mt = 0; mt < 4; mt++) {
                int rb = wm * 64 + mt * 16 + r;
                a[mt][0] = sm.g.As[(ko + cl) * 132 + rb];
                a[mt][1] = sm.g.As[(ko + cl) * 132 + rb + 8];
                a[mt][2] = sm.g.As[(ko + 4 + cl) * 132 + rb];
                a[mt][3] = sm.g.As[(ko + 4 + cl) * 132 + rb + 8];
            }
#pragma unroll
            for (int nt = 0; nt < 4; nt++) {
                int nb2 = wn * 32 + nt * 8 + r;
                bfr[nt][0] = sm.g.Bs[(ko + cl) * 132 + nb2];
                bfr[nt][1] = sm.g.Bs[(ko + 4 + cl) * 132 + nb2];
            }
#pragma unroll
            for (int mt = 0; mt < 4; mt++)
#pragma unroll
                for (int nt = 0; nt < 4; nt++)
                    mma_tf32(acc[mt][nt], a[mt], bfr[nt]);
        }
    }

    // add bias, write fp32 g_ht (coalesced)
    float* Og = g_ht + (size_t)bt * 65536;
#pragma unroll
    for (int mt = 0; mt < 4; mt++) {
        int row = wm * 64 + mt * 16 + r;
#pragma unroll
        for (int nt = 0; nt < 4; nt++) {
            int col = wn * 32 + nt * 8 + 2 * cl;
            float2 ob = *(const float2*)&in_b[h0 + col];
            acc[mt][nt][0] += ob.x;  acc[mt][nt][1] += ob.y;
            acc[mt][nt][2] += ob.x;  acc[mt][nt][3] += ob.y;
            *(float2*)(Og + (size_t)(n0 + row) * 256 + h0 + col)     = make_float2(acc[mt][nt][0], acc[mt][nt][1]);
            *(float2*)(Og + (size_t)(n0 + row + 8) * 256 + h0 + col) = make_float2(acc[mt][nt][2], acc[mt][nt][3]);
        }
    }

    // stage bf16 transpose in smem: tr[h][n]
    __syncthreads();
#pragma unroll
    for (int mt = 0; mt < 4; mt++) {
        int row = wm * 64 + mt * 16 + r;
#pragma unroll
        for (int nt = 0; nt < 4; nt++) {
            int col = wn * 32 + nt * 8 + 2 * cl;
            sm.tr[(col)     * 136 + row]     = __float2bfloat16(acc[mt][nt][0]);
            sm.tr[(col + 1) * 136 + row]     = __float2bfloat16(acc[mt][nt][1]);
            sm.tr[(col)     * 136 + row + 8] = __float2bfloat16(acc[mt][nt][2]);
            sm.tr[(col + 1) * 136 + row + 8] = __float2bfloat16(acc[mt][nt][3]);
        }
    }
    __syncthreads();
    // coalesced write to g_hbfT[b][t][h][n]
    __nv_bfloat16* Dst = g_hbfT + (size_t)bt * 65536;
#pragma unroll
    for (int p = 0; p < 32; p++) {
        int idx = tid + p * 256;
        int h = idx >> 6, np = idx & 63;
        uint32_t v = *(uint32_t*)&sm.tr[h * 136 + np * 2];
        *(uint32_t*)(Dst + (size_t)(h0 + h) * 256 + n0 + np * 2) = v;
    }
}

// ---------------- K2: bf16 mma GEMM, 3-stage cp.async, 1 sync/chunk ----------------
// out[b,t][i][h] = sum_lag sum_j (alpha*An)[b,lag][i][j] * h[b][t-lag][j][h]
__global__ __launch_bounds__(256, 2) void k_spatial_bf16() {
    __shared__ __align__(16) char sA[3][8192];
    __shared__ __align__(16) char sB[3][8192];
    int tid = threadIdx.x, lane = tid & 31, warp = tid >> 5;
    int i0 = blockIdx.x * 128, h0 = blockIdx.y * 128;
    int bt = blockIdx.z, b = bt >> 7, t = bt & 127;
    int wm = warp & 1, wn = warp >> 1;    // warp tile 64(m) x 32(n)

    float acc[4][4][4];
#pragma unroll
    for (int mt = 0; mt < 4; mt++)
#pragma unroll
        for (int nt = 0; nt < 4; nt++)
#pragma unroll
            for (int e = 0; e < 4; e++) acc[mt][nt][e] = 0.f;

    int nlag = (t + 1 < 8) ? (t + 1) : 8;
    int nch = nlag * 8;

    const char* Ab = (const char*)g_AbfS + (size_t)b * 8 * 131072 + (size_t)i0 * 512;
    const char* Hb = (const char*)g_hbfT + (size_t)(b * 128 + t) * 131072 + (size_t)h0 * 512;

    uint32_t sAb[3] = { smem_u32(sA[0]), smem_u32(sA[1]), smem_u32(sA[2]) };
    uint32_t sBb[3] = { smem_u32(sB[0]), smem_u32(sB[1]), smem_u32(sB[2]) };

    int lrow = tid >> 2, lcb = (tid & 3) * 16;
    int lswz = SWC(lrow, lcb);                 // rows 0..63 slot
    int gbyte0 = lrow * 512 + lcb;

    auto issue = [&](int c, int s) {
        int lag = c >> 3, j0b = (c & 7) * 64;
        const char* asrc = Ab + (size_t)lag * 131072 + j0b;
        const char* bsrc = Hb - (size_t)lag * 131072 + j0b;
        cp_async16(sAb[s] + lswz,        asrc + gbyte0);
        cp_async16(sAb[s] + lswz + 4096, asrc + gbyte0 + 32768);
        cp_async16(sBb[s] + lswz,        bsrc + gbyte0);
        cp_async16(sBb[s] + lswz + 4096, bsrc + gbyte0 + 32768);
        asm volatile("cp.async.commit_group;" ::: "memory");
    };

    issue(0, 0);
    issue(1, 1);

    int arow = wm * 64 + (lane & 15);
    int akb = (lane >> 4) * 16;                 // byte offset within k-chunk
    int brow = wn * 32 + (lane & 7) + (lane >> 4) * 8;
    int bkb = ((lane >> 3) & 1) * 16;

    int s = 0, sIss = 2;
    for (int c = 0; c < nch; ++c) {
        if (c == nch - 1) asm volatile("cp.async.wait_group 0;" ::: "memory");
        else              asm volatile("cp.async.wait_group 1;" ::: "memory");
        __syncthreads();
        if (c + 2 < nch) issue(c + 2, sIss);
#pragma unroll
        for (int ks = 0; ks < 2; ks++) {
            uint32_t a[4][4];
#pragma unroll
            for (int mt = 0; mt < 4; mt++)
                ldsm_x4(a[mt], sAb[s] + SWC(arow + mt * 16, ks * 32 + akb));
            uint32_t bb[2][4];
#pragma unroll
            for (int np = 0; np < 2; np++)
                ldsm_x4(bb[np], sBb[s] + SWC(brow + np * 16, ks * 32 + bkb));
#pragma unroll
            for (int mt = 0; mt < 4; mt++)
#pragma unroll
                for (int nt = 0; nt < 4; nt++) {
                    uint32_t bfr[2] = { bb[nt >> 1][(nt & 1) * 2], bb[nt >> 1][(nt & 1) * 2 + 1] };
                    mma_bf16(acc[mt][nt], a[mt], bfr);
                }
        }
        if (++s == 3) s = 0;
        if (++sIss == 3) sIss = 0;
    }

    int r = lane >> 2, cl = lane & 3;
    float* Og = g_agg + (size_t)bt * 65536;
#pragma unroll
    for (int mt = 0; mt < 4; mt++) {
        int row = i0 + wm * 64 + mt * 16 + r;
#pragma unroll
        for (int nt = 0; nt < 4; nt++) {
            int col = h0 + wn * 32 + nt * 8 + 2 * cl;
            *(float2*)(Og + (size_t)row * 256 + col)       = make_float2(acc[mt][nt][0], acc[mt][nt][1]);
            *(float2*)(Og + (size_t)(row + 8) * 256 + col) = make_float2(acc[mt][nt][2], acc[mt][nt][3]);
        }
    }
}

// ---------------- K3: out2 = agg@out_w + out_b; +h; LN; GELU; transpose (tf32 mma)
__global__ __launch_bounds__(256) void k_out_tc(const float* __restrict__ out_w,
                                                const float* __restrict__ out_b,
                                                const float* __restrict__ ln_g,
                                                const float* __restrict__ ln_b,
                                                float* __restrict__ out) {
    __shared__ uint32_t As[16 * 68];
    __shared__ uint32_t Bs[16 * 260];
    __shared__ float red[64 * 8];   // [row][wn][s/s2]
    int tid = threadIdx.x, lane = tid & 31, warp = tid >> 5;
    int r0 = blockIdx.x * 64;       // rows = (b*T + t)*N + n
    int wm = warp & 1, wn = warp >> 1;
    int r = lane >> 2, cl = lane & 3;

    float acc[2][8][4];
#pragma unroll
    for (int mt = 0; mt < 2; mt++)
#pragma unroll
        for (int nt = 0; nt < 8; nt++)
#pragma unroll
            for (int e = 0; e < 4; e++) acc[mt][nt][e] = 0.f;

    for (int kk = 0; kk < 256; kk += 16) {
        __syncthreads();
#pragma unroll
        for (int p = 0; p < 4; p++) {
            int idx = tid + p * 256;
            int row = idx >> 4, k = idx & 15;
            As[k * 68 + row] = f2tf(g_agg[(size_t)(r0 + row) * 256 + kk + k]);
        }
#pragma unroll
        for (int p = 0; p < 16; p++) {
            int idx = tid + p * 256;
            int k = idx >> 8, col = idx & 255;
            Bs[k * 260 + col] = f2tf(out_w[(kk + k) * 256 + col]);
        }
        __syncthreads();
#pragma unroll
        for (int ks = 0; ks < 2; ks++) {
            int ko = ks * 8;
            uint32_t a[2][4], bfr[8][2];
#pragma unroll
            for (int mt = 0; mt < 2; mt++) {
                int rb = wm * 32 + mt * 16 + r;
                a[mt][0] = As[(ko + cl) * 68 + rb];
                a[mt][1] = As[(ko + cl) * 68 + rb + 8];
                a[mt][2] = As[(ko + 4 + cl) * 68 + rb];
                a[mt][3] = As[(ko + 4 + cl) * 68 + rb + 8];
            }
#pragma unroll
            for (int nt = 0; nt < 8; nt++) {
                int nb = wn * 64 + nt * 8 + r;
                bfr[nt][0] = Bs[(ko + cl) * 260 + nb];
                bfr[nt][1] = Bs[(ko + 4 + cl) * 260 + nb];
            }
#pragma unroll
            for (int mt = 0; mt < 2; mt++)
#pragma unroll
                for (int nt = 0; nt < 8; nt++)
                    mma_tf32(acc[mt][nt], a[mt], bfr[nt]);
        }
    }

    // epilogue: residual + LN stats
#pragma unroll
    for (int mt = 0; mt < 2; mt++) {
#pragma unroll
        for (int rr = 0; rr < 2; rr++) {
            int row_local = wm * 32 + mt * 16 + rr * 8 + r;
            size_t rg = (size_t)r0 + row_local;
            const float* hrow = g_ht + rg * 256;
            float ss = 0.f, ss2 = 0.f;
#pragma unroll
            for (int nt = 0; nt < 8; nt++) {
                int col = wn * 64 + nt * 8 + 2 * cl;
                float2 hb = *(const float2*)&hrow[col];
                float2 ob = *(const float2*)&out_b[col];
                float v0 = acc[mt][nt][rr * 2 + 0] + ob.x + hb.x;
                float v1 = acc[mt][nt][rr * 2 + 1] + ob.y + hb.y;
                acc[mt][nt][rr * 2 + 0] = v0;
                acc[mt][nt][rr * 2 + 1] = v1;
                ss += v0 + v1;
                ss2 += v0 * v0 + v1 * v1;
            }
            ss += __shfl_xor_sync(0xffffffffu, ss, 1);
            ss2 += __shfl_xor_sync(0xffffffffu, ss2, 1);
            ss += __shfl_xor_sync(0xffffffffu, ss, 2);
            ss2 += __shfl_xor_sync(0xffffffffu, ss2, 2);
            if (cl == 0) {
                red[row_local * 8 + wn * 2 + 0] = ss;
                red[row_local * 8 + wn * 2 + 1] = ss2;
            }
        }
    }
    __syncthreads();
#pragma unroll
    for (int mt = 0; mt < 2; mt++) {
#pragma unroll
        for (int rr = 0; rr < 2; rr++) {
            int row_local = wm * 32 + mt * 16 + rr * 8 + r;
            float ts = 0.f, ts2 = 0.f;
#pragma unroll
            for (int w2 = 0; w2 < 4; w2++) {
                ts += red[row_local * 8 + w2 * 2 + 0];
                ts2 += red[row_local * 8 + w2 * 2 + 1];
            }
            float mu = ts * (1.0f / 256.0f);
            float var = ts2 * (1.0f / 256.0f) - mu * mu;
            float rs = rsqrtf(var + 1e-5f);
            int rg = r0 + row_local;
            int b_ = rg >> 15, t_ = (rg >> 8) & 127, n_ = rg & 255;
            float* orow = out + (((size_t)b_ * 256 + n_) * 128 + t_) * 256;
#pragma unroll
            for (int nt = 0; nt < 8; nt++) {
                int col = wn * 64 + nt * 8 + 2 * cl;
                float2 lg = *(const float2*)&ln_g[col];
                float2 lb = *(const float2*)&ln_b[col];
                float z0 = (acc[mt][nt][rr * 2 + 0] - mu) * rs * lg.x + lb.x;
                float z1 = (acc[mt][nt][rr * 2 + 1] - mu) * rs * lg.y + lb.y;
                *(float2*)&orow[col] = make_float2(gelu_f(z0), gelu_f(z1));
            }
        }
    }
}

extern "C" void kernel_launch(void* const* d_in, const int* in_sizes, int n_in,
                              void* d_out, int out_size) {
    const float* x       = (const float*)d_in[0];
    const float* A_list  = (const float*)d_in[1];
    const float* in_w    = (const float*)d_in[2];
    const float* in_b    = (const float*)d_in[3];
    const float* out_w   = (const float*)d_in[4];
    const float* out_b   = (const float*)d_in[5];
    const float* lag     = (const float*)d_in[6];
    const float* cw1     = (const float*)d_in[7];
    const float* cb1     = (const float*)d_in[8];
    const float* cw2     = (const float*)d_in[9];
    const float* cb2     = (const float*)d_in[10];
    const float* gw1     = (const float*)d_in[11];
    const float* gb1     = (const float*)d_in[12];
    const float* gw2     = (const float*)d_in[13];
    const float* gb2     = (const float*)d_in[14];
    const float* lng     = (const float*)d_in[15];
    const float* lnb     = (const float*)d_in[16];
    float* out = (float*)d_out;

    k_ctx_a<<<256, 256>>>(x);
    k_normA<<<2048, 256>>>(A_list);
    k_gate<<<1, 256>>>(lag, cw1, cb1, cw2, cb2, gw1, gb1, gw2, gb2);
    k_scaleA<<<2048, 256>>>();
    k_h2<<<dim3(2, 2, 512), 256>>>(x, in_w, in_b);
    k_spatial_bf16<<<dim3(2, 2, 512), 256>>>();
    k_out_tc<<<2048, 256>>>(out_w, out_b, lng, lnb, out);
}

// round 7
// speedup vs baseline: 2.9279x; 1.3361x over previous
#include <cuda_runtime.h>
#include <cuda_bf16.h>
#include <cstdint>
#include <math.h>

#define Bn 4
#define Nn 256
#define Tn 128
#define Fn 64
#define Kn 8
#define Hn 256

// ---------------- scratch (static device globals) ----------------
__device__ float g_ht[Bn*Tn*Nn*Hn];            // h: [b][t][n][h] fp32
__device__ __nv_bfloat16 g_aggbf[Bn*Tn*Nn*Hn]; // lag aggregate bf16: [bt*256+i][h]
__device__ __nv_bfloat16 g_AbfS[Bn*Kn*Nn*Nn];  // alpha-scaled normalized A bf16: [b][k][i][j]
__device__ __nv_bfloat16 g_hbfT[Bn*Tn*Hn*Nn];  // h bf16 transposed: [b][t][h][n]
__device__ __nv_bfloat16 g_owT[Hn*Hn];         // out_w transposed bf16: [o][h]
__device__ float g_part[256*256];              // ctx partial sums
__device__ float g_alpha[Bn*Kn];               // gate values

__device__ __forceinline__ float gelu_f(float v) {
    return 0.5f * v * (1.0f + erff(v * 0.7071067811865476f));
}

__device__ __forceinline__ uint32_t f2tf(float x) {
    uint32_t u;
    asm("cvt.rna.tf32.f32 %0, %1;" : "=r"(u) : "f"(x));
    return u;
}

__device__ __forceinline__ void mma_tf32(float (&d)[4], const uint32_t (&a)[4], const uint32_t (&b)[2]) {
    asm volatile(
        "mma.sync.aligned.m16n8k8.row.col.f32.tf32.tf32.f32 "
        "{%0,%1,%2,%3}, {%4,%5,%6,%7}, {%8,%9}, {%0,%1,%2,%3};"
        : "+f"(d[0]), "+f"(d[1]), "+f"(d[2]), "+f"(d[3])
        : "r"(a[0]), "r"(a[1]), "r"(a[2]), "r"(a[3]), "r"(b[0]), "r"(b[1]));
}

__device__ __forceinline__ void mma_bf16(float (&d)[4], const uint32_t (&a)[4], const uint32_t (&b)[2]) {
    asm volatile(
        "mma.sync.aligned.m16n8k16.row.col.f32.bf16.bf16.f32 "
        "{%0,%1,%2,%3}, {%4,%5,%6,%7}, {%8,%9}, {%0,%1,%2,%3};"
        : "+f"(d[0]), "+f"(d[1]), "+f"(d[2]), "+f"(d[3])
        : "r"(a[0]), "r"(a[1]), "r"(a[2]), "r"(a[3]), "r"(b[0]), "r"(b[1]));
}

__device__ __forceinline__ void ldsm_x4(uint32_t (&r)[4], uint32_t addr) {
    asm volatile("ldmatrix.sync.aligned.m8n8.x4.shared.b16 {%0,%1,%2,%3}, [%4];"
                 : "=r"(r[0]), "=r"(r[1]), "=r"(r[2]), "=r"(r[3]) : "r"(addr));
}

__device__ __forceinline__ uint32_t smem_u32(const void* p) {
    uint32_t a;
    asm("{ .reg .u64 t; cvta.to.shared.u64 t, %1; cvt.u32.u64 %0, t; }" : "=r"(a) : "l"(p));
    return a;
}

__device__ __forceinline__ void cp_async16(uint32_t dst, const void* src) {
    asm volatile("cp.async.cg.shared.global [%0], [%1], 16;" :: "r"(dst), "l"(src));
}

// swizzled byte offset within a [row][32 bf16] tile, rows 64B, 16B-chunk rotation
#define SWC(r, cb) (((r) << 6) + ((((((cb) >> 4) + (((r) >> 1) & 3))) & 3) << 4))

// ---------------- ctx mean stage 1 ----------------
__global__ void k_ctx_a(const float* __restrict__ x) {
    int tid = threadIdx.x;
    int idx0 = blockIdx.x * 256 + tid;
    __shared__ float sm[1024];
    float s[4];
#pragma unroll
    for (int b = 0; b < 4; b++) {
        float acc = 0.f;
        const float* p = x + b * 2097152 + idx0;
#pragma unroll 8
        for (int it = 0; it < 32; it++) acc += p[it * 65536];
        s[b] = acc;
    }
#pragma unroll
    for (int b = 0; b < 4; b++) sm[tid * 4 + b] = s[b];
    __syncthreads();
    int b = tid >> 6, f = tid & 63;
    float tot = sm[f * 4 + b] + sm[(f + 64) * 4 + b] + sm[(f + 128) * 4 + b] + sm[(f + 192) * 4 + b];
    g_part[blockIdx.x * 256 + tid] = tot;
}

// ---------------- ctx stage 2 + gate MLP fused -> alpha ----------------
__global__ void k_gate(const float* __restrict__ lag_embed,
                       const float* __restrict__ cw1, const float* __restrict__ cb1,
                       const float* __restrict__ cw2, const float* __restrict__ cb2,
                       const float* __restrict__ gw1, const float* __restrict__ gb1,
                       const float* __restrict__ gw2, const float* __restrict__ gb2) {
    __shared__ float ctx_sm[256];
    int tid = threadIdx.x;
    float s = 0.f;
    for (int blk = 0; blk < 256; blk++) s += g_part[blk * 256 + tid];
    ctx_sm[tid] = s * (1.0f / 32768.0f);
    __syncthreads();
    if (tid >= 32) return;
    int b = tid >> 3, kk = tid & 7;
    float e1[8];
#pragma unroll
    for (int e = 0; e < 8; e++) {
        float t = cb1[e];
        for (int f = 0; f < 64; f++) t += ctx_sm[b * 64 + f] * cw1[f * 8 + e];
        e1[e] = gelu_f(t);
    }
    float cf[8];
#pragma unroll
    for (int e2 = 0; e2 < 8; e2++) {
        float t = cb2[e2];
#pragma unroll
        for (int e = 0; e < 8; e++) t += e1[e] * cw2[e * 8 + e2];
        cf[e2] = t;
    }
    float gg[8];
#pragma unroll
    for (int e = 0; e < 8; e++) {
        float t = gb1[e];
#pragma unroll
        for (int i = 0; i < 16; i++) {
            float gi = (i < 8) ? lag_embed[kk * 8 + i] : cf[i - 8];
            t += gi * gw1[i * 8 + e];
        }
        gg[e] = gelu_f(t);
    }
    float o = gb2[0];
#pragma unroll
    for (int e = 0; e < 8; e++) o += gg[e] * gw2[e];
    g_alpha[b * 8 + kk] = 1.0f / (1.0f + expf(-o));
}

// ---------------- A row-normalize + alpha scale + bf16 cast (fused) ----------------
__global__ void k_prepA(const float* __restrict__ A_list) {
    int row = blockIdx.x;          // row = k*256 + i
    int tid = threadIdx.x;         // j
    float v = A_list[row * 256 + tid];
    float s = v;
#pragma unroll
    for (int o = 16; o > 0; o >>= 1) s += __shfl_xor_sync(0xffffffffu, s, o);
    __shared__ float red[8];
    __shared__ float invs;
    if ((tid & 31) == 0) red[tid >> 5] = s;
    __syncthreads();
    if (tid == 0) {
        float t = 0.f;
#pragma unroll
        for (int w = 0; w < 8; w++) t += red[w];
        invs = 1.0f / fmaxf(t, 1e-8f);
    }
    __syncthreads();
    float vn = v * invs;
    int k = row >> 8, i = row & 255;
#pragma unroll
    for (int b = 0; b < 4; b++) {
        float al = g_alpha[b * 8 + k];
        g_AbfS[((size_t)(b * 8 + k) * 256 + i) * 256 + tid] = __float2bfloat16(al * vn);
    }
}

// ---------------- out_w transpose -> bf16 g_owT[o][h] ----------------
__global__ void k_owT(const float* __restrict__ out_w) {
    __shared__ float tile[32][33];
    int h0 = blockIdx.x * 32, o0 = blockIdx.y * 32;
    int tx = threadIdx.x, ty = threadIdx.y;
#pragma unroll
    for (int p = 0; p < 4; p++)
        tile[ty + p * 8][tx] = out_w[(h0 + ty + p * 8) * 256 + o0 + tx];
    __syncthreads();
#pragma unroll
    for (int p = 0; p < 4; p++)
        g_owT[(size_t)(o0 + ty + p * 8) * 256 + h0 + tx] = __float2bfloat16(tile[tx][ty + p * 8]);
}

// ---------------- K1: h = x@in_w + in_b (tf32 mma), write g_ht fp32 + g_hbfT bf16^T
union SmemH {
    struct { uint32_t As[32 * 132]; uint32_t Bs[32 * 132]; } g;
    __nv_bfloat16 tr[128 * 136];
};

__global__ __launch_bounds__(256) void k_h2(const float* __restrict__ x,
                                            const float* __restrict__ in_w,
                                            const float* __restrict__ in_b) {
    __shared__ SmemH sm;
    int tid = threadIdx.x, lane = tid & 31, warp = tid >> 5;
    int n0 = blockIdx.x * 128, h0 = blockIdx.y * 128;
    int bt = blockIdx.z, b = bt >> 7, t = bt & 127;
    int wm = warp & 1, wn = warp >> 1;     // warp tile 64(n-rows) x 32(h-cols)
    int r = lane >> 2, cl = lane & 3;

    float acc[4][4][4];
#pragma unroll
    for (int mt = 0; mt < 4; mt++)
#pragma unroll
        for (int nt = 0; nt < 4; nt++)
#pragma unroll
            for (int e = 0; e < 4; e++) acc[mt][nt][e] = 0.f;

    for (int f0 = 0; f0 < 64; f0 += 32) {
        __syncthreads();
        {   // x tile -> As[f][n] (tf32)
            int f = tid & 31, nb = tid >> 5;
            const float* xb = x + (((size_t)(b * 256 + n0) * 128 + t) * 64) + f0 + f;
#pragma unroll
            for (int p = 0; p < 16; p++) {
                int nn = nb + p * 8;
                sm.g.As[f * 132 + nn] = f2tf(xb[(size_t)nn * 8192]);
            }
        }
        {   // w tile -> Bs[f][h] (tf32)
#pragma unroll
            for (int p = 0; p < 16; p++) {
                int idx = tid + p * 256;
                int f = idx >> 7, c = idx & 127;
                sm.g.Bs[f * 132 + c] = f2tf(in_w[(f0 + f) * 256 + h0 + c]);
            }
        }
        __syncthreads();
#pragma unroll
        for (int ks = 0; ks < 4; ks++) {
            int ko = ks * 8;
            uint32_t a[4][4], bfr[4][2];
#pragma unroll
            for (int mt = 0; mt < 4; mt++) {
                int rb = wm * 64 + mt * 16 + r;
                a[mt][0] = sm.g.As[(ko + cl) * 132 + rb];
                a[mt][1] = sm.g.As[(ko + cl) * 132 + rb + 8];
                a[mt][2] = sm.g.As[(ko + 4 + cl) * 132 + rb];
                a[mt][3] = sm.g.As[(ko + 4 + cl) * 132 + rb + 8];
            }
#pragma unroll
            for (int nt = 0; nt < 4; nt++) {
                int nb2 = wn * 32 + nt * 8 + r;
                bfr[nt][0] = sm.g.Bs[(ko + cl) * 132 + nb2];
                bfr[nt][1] = sm.g.Bs[(ko + 4 + cl) * 132 + nb2];
            }
#pragma unroll
            for (int mt = 0; mt < 4; mt++)
#pragma unroll
                for (int nt = 0; nt < 4; nt++)
                    mma_tf32(acc[mt][nt], a[mt], bfr[nt]);
        }
    }

    // add bias, write fp32 g_ht (coalesced)
    float* Og = g_ht + (size_t)bt * 65536;
#pragma unroll
    for (int mt = 0; mt < 4; mt++) {
        int row = wm * 64 + mt * 16 + r;
#pragma unroll
        for (int nt = 0; nt < 4; nt++) {
            int col = wn * 32 + nt * 8 + 2 * cl;
            float2 ob = *(const float2*)&in_b[h0 + col];
            acc[mt][nt][0] += ob.x;  acc[mt][nt][1] += ob.y;
            acc[mt][nt][2] += ob.x;  acc[mt][nt][3] += ob.y;
            *(float2*)(Og + (size_t)(n0 + row) * 256 + h0 + col)     = make_float2(acc[mt][nt][0], acc[mt][nt][1]);
            *(float2*)(Og + (size_t)(n0 + row + 8) * 256 + h0 + col) = make_float2(acc[mt][nt][2], acc[mt][nt][3]);
        }
    }

    // stage bf16 transpose in smem: tr[h][n]
    __syncthreads();
#pragma unroll
    for (int mt = 0; mt < 4; mt++) {
        int row = wm * 64 + mt * 16 + r;
#pragma unroll
        for (int nt = 0; nt < 4; nt++) {
            int col = wn * 32 + nt * 8 + 2 * cl;
            sm.tr[(col)     * 136 + row]     = __float2bfloat16(acc[mt][nt][0]);
            sm.tr[(col + 1) * 136 + row]     = __float2bfloat16(acc[mt][nt][1]);
            sm.tr[(col)     * 136 + row + 8] = __float2bfloat16(acc[mt][nt][2]);
            sm.tr[(col + 1) * 136 + row + 8] = __float2bfloat16(acc[mt][nt][3]);
        }
    }
    __syncthreads();
    __nv_bfloat16* Dst = g_hbfT + (size_t)bt * 65536;
#pragma unroll
    for (int p = 0; p < 32; p++) {
        int idx = tid + p * 256;
        int h = idx >> 6, np = idx & 63;
        uint32_t v = *(uint32_t*)&sm.tr[h * 136 + np * 2];
        *(uint32_t*)(Dst + (size_t)(h0 + h) * 256 + n0 + np * 2) = v;
    }
}

// ---------------- K2: bf16 mma GEMM, 3-stage cp.async, bf16 agg output ----------------
__global__ __launch_bounds__(256, 2) void k_spatial_bf16() {
    __shared__ __align__(16) char sA[3][8192];
    __shared__ __align__(16) char sB[3][8192];
    int tid = threadIdx.x, lane = tid & 31, warp = tid >> 5;
    int i0 = blockIdx.x * 128, h0 = blockIdx.y * 128;
    int bt = blockIdx.z, b = bt >> 7, t = bt & 127;
    int wm = warp & 1, wn = warp >> 1;    // warp tile 64(m) x 32(n)

    float acc[4][4][4];
#pragma unroll
    for (int mt = 0; mt < 4; mt++)
#pragma unroll
        for (int nt = 0; nt < 4; nt++)
#pragma unroll
            for (int e = 0; e < 4; e++) acc[mt][nt][e] = 0.f;

    int nlag = (t + 1 < 8) ? (t + 1) : 8;
    int nch = nlag * 8;

    const char* Ab = (const char*)g_AbfS + (size_t)b * 8 * 131072 + (size_t)i0 * 512;
    const char* Hb = (const char*)g_hbfT + (size_t)(b * 128 + t) * 131072 + (size_t)h0 * 512;

    uint32_t sAb[3] = { smem_u32(sA[0]), smem_u32(sA[1]), smem_u32(sA[2]) };
    uint32_t sBb[3] = { smem_u32(sB[0]), smem_u32(sB[1]), smem_u32(sB[2]) };

    int lrow = tid >> 2, lcb = (tid & 3) * 16;
    int lswz = SWC(lrow, lcb);
    int gbyte0 = lrow * 512 + lcb;

    auto issue = [&](int c, int s) {
        int lag = c >> 3, j0b = (c & 7) * 64;
        const char* asrc = Ab + (size_t)lag * 131072 + j0b;
        const char* bsrc = Hb - (size_t)lag * 131072 + j0b;
        cp_async16(sAb[s] + lswz,        asrc + gbyte0);
        cp_async16(sAb[s] + lswz + 4096, asrc + gbyte0 + 32768);
        cp_async16(sBb[s] + lswz,        bsrc + gbyte0);
        cp_async16(sBb[s] + lswz + 4096, bsrc + gbyte0 + 32768);
        asm volatile("cp.async.commit_group;" ::: "memory");
    };

    issue(0, 0);
    issue(1, 1);

    int arow = wm * 64 + (lane & 15);
    int akb = (lane >> 4) * 16;
    int brow = wn * 32 + (lane & 7) + (lane >> 4) * 8;
    int bkb = ((lane >> 3) & 1) * 16;

    int s = 0, sIss = 2;
    for (int c = 0; c < nch; ++c) {
        if (c == nch - 1) asm volatile("cp.async.wait_group 0;" ::: "memory");
        else              asm volatile("cp.async.wait_group 1;" ::: "memory");
        __syncthreads();
        if (c + 2 < nch) issue(c + 2, sIss);
#pragma unroll
        for (int ks = 0; ks < 2; ks++) {
            uint32_t a[4][4];
#pragma unroll
            for (int mt = 0; mt < 4; mt++)
                ldsm_x4(a[mt], sAb[s] + SWC(arow + mt * 16, ks * 32 + akb));
            uint32_t bb[2][4];
#pragma unroll
            for (int np = 0; np < 2; np++)
                ldsm_x4(bb[np], sBb[s] + SWC(brow + np * 16, ks * 32 + bkb));
#pragma unroll
            for (int mt = 0; mt < 4; mt++)
#pragma unroll
                for (int nt = 0; nt < 4; nt++) {
                    uint32_t bfr[2] = { bb[nt >> 1][(nt & 1) * 2], bb[nt >> 1][(nt & 1) * 2 + 1] };
                    mma_bf16(acc[mt][nt], a[mt], bfr);
                }
        }
        if (++s == 3) s = 0;
        if (++sIss == 3) sIss = 0;
    }

    int r = lane >> 2, cl = lane & 3;
    __nv_bfloat16* Og = g_aggbf + (size_t)bt * 65536;
#pragma unroll
    for (int mt = 0; mt < 4; mt++) {
        int row = i0 + wm * 64 + mt * 16 + r;
#pragma unroll
        for (int nt = 0; nt < 4; nt++) {
            int col = h0 + wn * 32 + nt * 8 + 2 * cl;
            __nv_bfloat162 v0 = make_bfloat162(__float2bfloat16(acc[mt][nt][0]), __float2bfloat16(acc[mt][nt][1]));
            __nv_bfloat162 v1 = make_bfloat162(__float2bfloat16(acc[mt][nt][2]), __float2bfloat16(acc[mt][nt][3]));
            *(__nv_bfloat162*)(Og + (size_t)row * 256 + col)       = v0;
            *(__nv_bfloat162*)(Og + (size_t)(row + 8) * 256 + col) = v1;
        }
    }
}

// ---------------- K3: out2 = agg@out_w (bf16 mma); +out_b +h; LN; GELU; transpose
__global__ __launch_bounds__(256) void k_out_bf16(const float* __restrict__ out_b,
                                                  const float* __restrict__ ln_g,
                                                  const float* __restrict__ ln_b,
                                                  float* __restrict__ out) {
    __shared__ __align__(16) char sA[2][4096];    // 64 rows x 64B
    __shared__ __align__(16) char sB[2][16384];   // 256 rows(o) x 64B
    __shared__ float red[64 * 16];                // [row][warp][s,s2]
    int tid = threadIdx.x, lane = tid & 31, warp = tid >> 5;
    int r0 = blockIdx.x * 64;                     // rows = bt*256 + n
    int r = lane >> 2, cl = lane & 3;

    float acc[4][4][4];
#pragma unroll
    for (int mt = 0; mt < 4; mt++)
#pragma unroll
        for (int nt = 0; nt < 4; nt++)
#pragma unroll
            for (int e = 0; e < 4; e++) acc[mt][nt][e] = 0.f;

    uint32_t sAb[2] = { smem_u32(sA[0]), smem_u32(sA[1]) };
    uint32_t sBb[2] = { smem_u32(sB[0]), smem_u32(sB[1]) };

    const char* Abase = (const char*)g_aggbf + (size_t)r0 * 512;
    const char* Bbase = (const char*)g_owT;

    int lrow = tid >> 2, lcb = (tid & 3) * 16;
    int lswz = SWC(lrow, lcb);

    auto issue = [&](int c, int s) {
        int j0b = c * 64;
        cp_async16(sAb[s] + lswz, Abase + (size_t)lrow * 512 + j0b + lcb);
#pragma unroll
        for (int p = 0; p < 4; p++) {
            int row = lrow + p * 64;
            cp_async16(sBb[s] + SWC(row, lcb), Bbase + (size_t)row * 512 + j0b + lcb);
        }
        asm volatile("cp.async.commit_group;" ::: "memory");
    };

    issue(0, 0);
    issue(1, 1);

    int arow = lane & 15;
    int akb = (lane >> 4) * 16;
    int brow = warp * 32 + (lane & 7) + (lane >> 4) * 8;
    int bkb = ((lane >> 3) & 1) * 16;

    for (int c = 0; c < 8; ++c) {
        int s = c & 1;
        if (c == 7) asm volatile("cp.async.wait_group 0;" ::: "memory");
        else        asm volatile("cp.async.wait_group 1;" ::: "memory");
        __syncthreads();
#pragma unroll
        for (int ks = 0; ks < 2; ks++) {
            uint32_t a[4][4];
#pragma unroll
            for (int mt = 0; mt < 4; mt++)
                ldsm_x4(a[mt], sAb[s] + SWC(arow + mt * 16, ks * 32 + akb));
            uint32_t bb[2][4];
#pragma unroll
            for (int np = 0; np < 2; np++)
                ldsm_x4(bb[np], sBb[s] + SWC(brow + np * 16, ks * 32 + bkb));
#pragma unroll
            for (int mt = 0; mt < 4; mt++)
#pragma unroll
                for (int nt = 0; nt < 4; nt++) {
                    uint32_t bfr[2] = { bb[nt >> 1][(nt & 1) * 2], bb[nt >> 1][(nt & 1) * 2 + 1] };
                    mma_bf16(acc[mt][nt], a[mt], bfr);
                }
        }
        __syncthreads();
        if (c + 2 < 8) issue(c + 2, s);
    }

    // epilogue: residual + LN stats.  rows: mt*16 + rr*8 + r ; cols: warp*32 + nt*8 + 2cl
#pragma unroll
    for (int mt = 0; mt < 4; mt++) {
#pragma unroll
        for (int rr = 0; rr < 2; rr++) {
            int row_local = mt * 16 + rr * 8 + r;
            size_t rg = (size_t)r0 + row_local;
            const float* hrow = g_ht + rg * 256;
            float ss = 0.f, ss2 = 0.f;
#pragma unroll
            for (int nt = 0; nt < 4; nt++) {
                int col = warp * 32 + nt * 8 + 2 * cl;
                float2 hb = *(const float2*)&hrow[col];
                float2 ob = *(const float2*)&out_b[col];
                float v0 = acc[mt][nt][rr * 2 + 0] + ob.x + hb.x;
                float v1 = acc[mt][nt][rr * 2 + 1] + ob.y + hb.y;
                acc[mt][nt][rr * 2 + 0] = v0;
                acc[mt][nt][rr * 2 + 1] = v1;
                ss += v0 + v1;
                ss2 += v0 * v0 + v1 * v1;
            }
            ss += __shfl_xor_sync(0xffffffffu, ss, 1);
            ss2 += __shfl_xor_sync(0xffffffffu, ss2, 1);
            ss += __shfl_xor_sync(0xffffffffu, ss, 2);
            ss2 += __shfl_xor_sync(0xffffffffu, ss2, 2);
            if (cl == 0) {
                red[row_local * 16 + warp * 2 + 0] = ss;
                red[row_local * 16 + warp * 2 + 1] = ss2;
            }
        }
    }
    __syncthreads();
#pragma unroll
    for (int mt = 0; mt < 4; mt++) {
#pragma unroll
        for (int rr = 0; rr < 2; rr++) {
            int row_local = mt * 16 + rr * 8 + r;
            float ts = 0.f, ts2 = 0.f;
#pragma unroll
            for (int w2 = 0; w2 < 8; w2++) {
                ts += red[row_local * 16 + w2 * 2 + 0];
                ts2 += red[row_local * 16 + w2 * 2 + 1];
            }
            float mu = ts * (1.0f / 256.0f);
            float var = ts2 * (1.0f / 256.0f) - mu * mu;
            float rs = rsqrtf(var + 1e-5f);
            int rg = r0 + row_local;
            int b_ = rg >> 15, t_ = (rg >> 8) & 127, n_ = rg & 255;
            float* orow = out + (((size_t)b_ * 256 + n_) * 128 + t_) * 256;
#pragma unroll
            for (int nt = 0; nt < 4; nt++) {
                int col = warp * 32 + nt * 8 + 2 * cl;
                float2 lg = *(const float2*)&ln_g[col];
                float2 lb = *(const float2*)&ln_b[col];
                float z0 = (acc[mt][nt][rr * 2 + 0] - mu) * rs * lg.x + lb.x;
                float z1 = (acc[mt][nt][rr * 2 + 1] - mu) * rs * lg.y + lb.y;
                *(float2*)&orow[col] = make_float2(gelu_f(z0), gelu_f(z1));
            }
        }
    }
}

extern "C" void kernel_launch(void* const* d_in, const int* in_sizes, int n_in,
                              void* d_out, int out_size) {
    const float* x       = (const float*)d_in[0];
    const float* A_list  = (const float*)d_in[1];
    const float* in_w    = (const float*)d_in[2];
    const float* in_b    = (const float*)d_in[3];
    const float* out_w   = (const float*)d_in[4];
    const float* out_b   = (const float*)d_in[5];
    const float* lag     = (const float*)d_in[6];
    const float* cw1     = (const float*)d_in[7];
    const float* cb1     = (const float*)d_in[8];
    const float* cw2     = (const float*)d_in[9];
    const float* cb2     = (const float*)d_in[10];
    const float* gw1     = (const float*)d_in[11];
    const float* gb1     = (const float*)d_in[12];
    const float* gw2     = (const float*)d_in[13];
    const float* gb2     = (const float*)d_in[14];
    const float* lng     = (const float*)d_in[15];
    const float* lnb     = (const float*)d_in[16];
    float* out = (float*)d_out;

    k_ctx_a<<<256, 256>>>(x);
    k_gate<<<1, 256>>>(lag, cw1, cb1, cw2, cb2, gw1, gb1, gw2, gb2);
    k_prepA<<<2048, 256>>>(A_list);
    k_owT<<<dim3(8, 8), dim3(32, 8)>>>(out_w);
    k_h2<<<dim3(2, 2, 512), 256>>>(x, in_w, in_b);
    k_spatial_bf16<<<dim3(2, 2, 512), 256>>>();
    k_out_bf16<<<2048, 256>>>(out_b, lng, lnb, out);
}